// round 16
// baseline (speedup 1.0000x reference)
#include <cuda_runtime.h>
#include <cuda_bf16.h>
#include <math.h>
#include <stdint.h>

// Shapes fixed by the reference:
//   x  : (N, T, D) = (128, 512, 1024)
//   h0 : (N, H)    = (128, 1024)
//   Wx : (D, H), Wh : (H, H), b : (H)
//   out: (N, T, H) fp32

#define RNN_N 128
#define RNN_T 512
#define RNN_D 1024
#define RNN_H 1024

#define OUT_RSTRIDE ((size_t)RNN_T * RNN_H)

// Phase 2 geometry (R7 — best known)
#define P2_NCTAS 128
#define P2_BM 32
#define P2_BN 32
#define P2_LDB 1032
#define P2_LDA 136
#define P2_ABUF (P2_BM * P2_LDA)
#define P2_REDLD 34

// Split, transposed weights ([n][k] layout)
__device__ __nv_bfloat16 g_Wxt_hi[RNN_H * RNN_D];
__device__ __nv_bfloat16 g_Wxt_lo[RNN_H * RNN_D];
__device__ __nv_bfloat16 g_Wht_hi[RNN_H * RNN_H];
__device__ __nv_bfloat16 g_Wht_lo[RNN_H * RNN_H];

// Pre-split x (bf16 hi/lo), row-major (M, D) with M = N*T
__device__ __nv_bfloat16 g_x_hi[(size_t)RNN_N * RNN_T * RNN_D];
__device__ __nv_bfloat16 g_x_lo[(size_t)RNN_N * RNN_T * RNN_D];

// Barrier state: per-group 4 sub-counters (8 CTAs each) + master + gen,
// each on its own 128B line (stride 32 words).
__device__ unsigned g_bar_sub[4 * 4 * 32];
__device__ unsigned g_bar_master[4 * 32];
__device__ volatile unsigned g_bar_gen[4 * 32];

// ---------------------------------------------------------------------------
// helpers
// ---------------------------------------------------------------------------
__device__ __forceinline__ uint32_t cvta_smem(const void* p) {
    uint32_t a;
    asm("{ .reg .u64 t; cvta.to.shared.u64 t, %1; cvt.u32.u64 %0, t; }"
        : "=r"(a) : "l"(p));
    return a;
}

__device__ __forceinline__ void ldsm_x4(uint32_t& r0, uint32_t& r1,
                                        uint32_t& r2, uint32_t& r3,
                                        uint32_t addr) {
    asm volatile("ldmatrix.sync.aligned.m8n8.x4.shared.b16 {%0,%1,%2,%3}, [%4];"
        : "=r"(r0), "=r"(r1), "=r"(r2), "=r"(r3) : "r"(addr));
}

__device__ __forceinline__ void mma_bf16(float c[4],
    uint32_t a0, uint32_t a1, uint32_t a2, uint32_t a3,
    uint32_t b0, uint32_t b1)
{
    asm volatile(
        "mma.sync.aligned.m16n8k16.row.col.f32.bf16.bf16.f32 "
        "{%0,%1,%2,%3}, {%4,%5,%6,%7}, {%8,%9}, {%0,%1,%2,%3};"
        : "+f"(c[0]), "+f"(c[1]), "+f"(c[2]), "+f"(c[3])
        : "r"(a0), "r"(a1), "r"(a2), "r"(a3), "r"(b0), "r"(b1));
}

__device__ __forceinline__ void split4(const float4 v,
    __nv_bfloat162& h0, __nv_bfloat162& h1,
    __nv_bfloat162& l0, __nv_bfloat162& l1)
{
    h0 = __floats2bfloat162_rn(v.x, v.y);
    h1 = __floats2bfloat162_rn(v.z, v.w);
    l0 = __floats2bfloat162_rn(v.x - __bfloat162float(h0.x),
                               v.y - __bfloat162float(h0.y));
    l1 = __floats2bfloat162_rn(v.z - __bfloat162float(h1.x),
                               v.w - __bfloat162float(h1.y));
}

__device__ __forceinline__ void cp16(uint32_t dst, const void* src) {
    asm volatile("cp.async.cg.shared.global [%0], [%1], 16;"
                 :: "r"(dst), "l"(src));
}
#define CP_COMMIT() asm volatile("cp.async.commit_group;")
#define CP_WAIT1()  asm volatile("cp.async.wait_group 1;")

#define NAMED_BAR(id) asm volatile("bar.sync %0, 128;" :: "r"(id) : "memory")

// ---------------------------------------------------------------------------
// Weight convert: W (K x N, row-major) -> Wt_hi/lo (N x K, bf16 split)
// ---------------------------------------------------------------------------
__global__ __launch_bounds__(256) void convert_w_kernel(
    const float* __restrict__ W,
    __nv_bfloat16* __restrict__ Wt_hi,
    __nv_bfloat16* __restrict__ Wt_lo,
    int K, int N)
{
    __shared__ float tile[32][33];
    const int k0 = blockIdx.y * 32;
    const int n0 = blockIdx.x * 32;
    const int tx = threadIdx.x;
    const int ty = threadIdx.y;

#pragma unroll
    for (int i = 0; i < 32; i += 8)
        tile[ty + i][tx] = W[(size_t)(k0 + ty + i) * N + n0 + tx];
    __syncthreads();

#pragma unroll
    for (int i = 0; i < 32; i += 8) {
        float v = tile[tx][ty + i];
        __nv_bfloat16 h = __float2bfloat16(v);
        __nv_bfloat16 l = __float2bfloat16(v - __bfloat162float(h));
        size_t idx = (size_t)(n0 + ty + i) * K + (k0 + tx);
        Wt_hi[idx] = h;
        Wt_lo[idx] = l;
    }
}

// ---------------------------------------------------------------------------
// Split x into bf16 hi/lo global buffers (one float4 per thread)
// ---------------------------------------------------------------------------
__global__ __launch_bounds__(256) void split_x_kernel(
    const float* __restrict__ x,
    __nv_bfloat16* __restrict__ xhi,
    __nv_bfloat16* __restrict__ xlo)
{
    const size_t i = ((size_t)blockIdx.x * blockDim.x + threadIdx.x) * 4;
    float4 v = *(const float4*)(x + i);
    __nv_bfloat162 h0, h1, l0, l1;
    split4(v, h0, h1, l0, l1);
    uint2 hv; hv.x = *(uint32_t*)&h0; hv.y = *(uint32_t*)&h1;
    uint2 lv; lv.x = *(uint32_t*)&l0; lv.y = *(uint32_t*)&l1;
    *(uint2*)(xhi + i) = hv;
    *(uint2*)(xlo + i) = lv;
}

// ---------------------------------------------------------------------------
// Phase 1 (R7 exact, 1.105ms): out = x @ Wx + b, all-bf16, cp.async 3-stage.
// CTA 64x128, BK=32, 512 thr (16 warps 4m x 4n), warp tile 16x32.
// ---------------------------------------------------------------------------
#define Q1_LDK 40
#define Q1_AT (64 * Q1_LDK)
#define Q1_BT (128 * Q1_LDK)

__global__ __launch_bounds__(512) void gemm_xw_hmma(
    const float* __restrict__ bias,
    float* __restrict__ C)
{
    extern __shared__ __nv_bfloat16 q1sm[];
    __nv_bfloat16* AsHi = q1sm;
    __nv_bfloat16* AsLo = AsHi + 3 * Q1_AT;
    __nv_bfloat16* BsHi = AsLo + 3 * Q1_AT;
    __nv_bfloat16* BsLo = BsHi + 3 * Q1_BT;

    const int tid  = threadIdx.x;
    const int warp = tid >> 5;
    const int lane = tid & 31;
    const int g  = lane >> 2;
    const int tg = lane & 3;
    const int wm = (warp & 3) * 16;
    const int wn = (warp >> 2) * 32;

    const int brow = blockIdx.y * 64;
    const int bcol = blockIdx.x * 128;

    const int lrow = tid >> 2;
    const int lseg = (tid & 3) * 8;

    const __nv_bfloat16* Ahp = g_x_hi + (size_t)(brow + lrow) * RNN_D + lseg;
    const __nv_bfloat16* Alp = g_x_lo + (size_t)(brow + lrow) * RNN_D + lseg;
    const __nv_bfloat16* Bhp = g_Wxt_hi + (size_t)(bcol + lrow) * RNN_D + lseg;
    const __nv_bfloat16* Blp = g_Wxt_lo + (size_t)(bcol + lrow) * RNN_D + lseg;

    const uint32_t aDstHi = cvta_smem(AsHi) + (lrow * Q1_LDK + lseg) * 2;
    const uint32_t aDstLo = aDstHi + 3 * Q1_AT * 2;
    const uint32_t bDstHi = cvta_smem(BsHi) + (lrow * Q1_LDK + lseg) * 2;
    const uint32_t bDstLo = bDstHi + 3 * Q1_BT * 2;

    const uint32_t aHi0 = cvta_smem(AsHi) +
        (((wm + (lane & 15)) * Q1_LDK + ((lane >> 4) & 1) * 8) * 2);
    const uint32_t aLo0 = aHi0 + 3 * Q1_AT * 2;
    const uint32_t bHi0 = cvta_smem(BsHi) +
        (((wn + (lane & 7) + ((lane >> 4) & 1) * 8) * Q1_LDK +
          ((lane >> 3) & 1) * 8) * 2);
    const uint32_t bLo0 = bHi0 + 3 * Q1_BT * 2;

    float acc[4][4];
#pragma unroll
    for (int j = 0; j < 4; j++)
#pragma unroll
        for (int i = 0; i < 4; i++) acc[j][i] = 0.0f;

    auto issue = [&](int s) {
        const int buf = s % 3;
        const int kt = s * 32;
        if (tid < 256) {
            cp16(aDstHi + buf * (Q1_AT * 2), Ahp + kt);
            cp16(aDstLo + buf * (Q1_AT * 2), Alp + kt);
        }
        cp16(bDstHi + buf * (Q1_BT * 2), Bhp + kt);
        cp16(bDstLo + buf * (Q1_BT * 2), Blp + kt);
    };

    issue(0); CP_COMMIT();
    issue(1); CP_COMMIT();

    for (int i = 0; i < 32; ++i) {
        CP_WAIT1();
        __syncthreads();
        if (i + 2 < 32) issue(i + 2);
        CP_COMMIT();

        const uint32_t aoff = (uint32_t)(i % 3) * (Q1_AT * 2);
        const uint32_t boff = (uint32_t)(i % 3) * (Q1_BT * 2);
#pragma unroll
        for (int ks = 0; ks < 2; ++ks) {
            uint32_t ah0, ah1, ah2, ah3, al0, al1, al2, al3;
            ldsm_x4(ah0, ah1, ah2, ah3, aHi0 + aoff + ks * 32);
            ldsm_x4(al0, al1, al2, al3, aLo0 + aoff + ks * 32);
#pragma unroll
            for (int pr = 0; pr < 2; ++pr) {
                uint32_t bh0, bh1, bh2, bh3, bl0, bl1, bl2, bl3;
                ldsm_x4(bh0, bh1, bh2, bh3, bHi0 + boff + pr * (16 * Q1_LDK * 2) + ks * 32);
                ldsm_x4(bl0, bl1, bl2, bl3, bLo0 + boff + pr * (16 * Q1_LDK * 2) + ks * 32);
                mma_bf16(acc[2 * pr],     ah0, ah1, ah2, ah3, bh0, bh1);
                mma_bf16(acc[2 * pr],     ah0, ah1, ah2, ah3, bl0, bl1);
                mma_bf16(acc[2 * pr],     al0, al1, al2, al3, bh0, bh1);
                mma_bf16(acc[2 * pr + 1], ah0, ah1, ah2, ah3, bh2, bh3);
                mma_bf16(acc[2 * pr + 1], ah0, ah1, ah2, ah3, bl2, bl3);
                mma_bf16(acc[2 * pr + 1], al0, al1, al2, al3, bh2, bh3);
            }
        }
    }

#pragma unroll
    for (int j = 0; j < 4; j++) {
        const int col = bcol + wn + j * 8 + tg * 2;
        const float b0 = __ldg(bias + col);
        const float b1 = __ldg(bias + col + 1);
        const int r0 = brow + wm + g;
        float2 o0 = make_float2(acc[j][0] + b0, acc[j][1] + b1);
        float2 o1 = make_float2(acc[j][2] + b0, acc[j][3] + b1);
        *(float2*)&C[(size_t)r0 * RNN_H + col]       = o0;
        *(float2*)&C[(size_t)(r0 + 8) * RNN_H + col] = o1;
    }
}

// ---------------------------------------------------------------------------
// Per-row-group barrier with two-level arrival tree:
// 32 CTAs -> 4 sub-counters (8 each, separate lines) -> 1 master -> gen.
// Wait side unchanged: one poller per CTA on the gen word.
// ---------------------------------------------------------------------------
__device__ __forceinline__ void group_barrier(int grp, int col)
{
    __syncthreads();
    if (threadIdx.x == 0) {
        const int s = grp * 32;
        __threadfence();
        unsigned gen = g_bar_gen[s];
        unsigned* sub = &g_bar_sub[(grp * 4 + (col & 3)) * 32];
        unsigned old = atomicAdd(sub, 1u);
        if (old == 7u) {
            *sub = 0u;   // safe: next arrivals here only after gen flips
            unsigned old2 = atomicAdd(&g_bar_master[s], 1u);
            if (old2 == 3u) {
                g_bar_master[s] = 0u;
                __threadfence();
                g_bar_gen[s] = gen + 1;
            }
        }
        while (g_bar_gen[s] == gen) { }
        __threadfence();
    }
    __syncthreads();
}

// ---------------------------------------------------------------------------
// Phase 2 persistent kernel — R7 structure (best known), tree barrier.
// ---------------------------------------------------------------------------
__global__ __launch_bounds__(512) void rnn_persistent(
    const float* __restrict__ h0,
    float* __restrict__ out)
{
    extern __shared__ char sm[];
    __nv_bfloat16* Bs_hi = (__nv_bfloat16*)sm;
    __nv_bfloat16* Bs_lo = Bs_hi + P2_BN * P2_LDB;
    __nv_bfloat16* A_all = Bs_lo + P2_BN * P2_LDB;
    float* red = (float*)(A_all + 4 * 2 * P2_ABUF);

    const int tid  = threadIdx.x;
    const int warp = tid >> 5;
    const int lane = tid & 31;
    const int g  = lane >> 2;
    const int tg = lane & 3;
    const int kg = warp >> 2;
    const int w2 = warp & 3;
    const int wm = (w2 & 1) * 16;
    const int wn = (w2 >> 1) * 16;

    const int bx   = blockIdx.x;
    const int col_ = bx & 31;
    const int bcol = col_ * P2_BN;
    const int grp  = bx >> 5;
    const int brow = grp * P2_BM;

    {
        const uint4* GH = (const uint4*)(g_Wht_hi + (size_t)bcol * RNN_H);
        const uint4* GL = (const uint4*)(g_Wht_lo + (size_t)bcol * RNN_H);
        for (int idx = tid; idx < 4096; idx += 512) {
            const int r  = idx >> 7;
            const int k8 = (idx & 127) * 8;
            uint4 vh = GH[(size_t)r * 128 + (idx & 127)];
            uint4 vl = GL[(size_t)r * 128 + (idx & 127)];
            *(uint4*)((char*)Bs_hi + r * (P2_LDB * 2) + k8 * 2) = vh;
            *(uint4*)((char*)Bs_lo + r * (P2_LDB * 2) + k8 * 2) = vl;
        }
    }
    __syncthreads();

    __nv_bfloat16* Ah = A_all + kg * (2 * P2_ABUF);
    __nv_bfloat16* Al = Ah + P2_ABUF;

    const uint32_t aHi = cvta_smem(Ah) +
        (((wm + (lane & 15)) * P2_LDA + ((lane >> 4) & 1) * 8) * 2);
    const uint32_t aLo = aHi + P2_ABUF * 2;
    const uint32_t bHi = cvta_smem(Bs_hi) +
        (((wn + (lane & 7) + ((lane >> 4) & 1) * 8) * P2_LDB +
          ((lane >> 3) & 1) * 8) * 2);
    const uint32_t bLo = bHi + (P2_BN * P2_LDB) * 2;

    const int tkg = tid & 127;
    const int lr  = tkg >> 2;
    const int lc4 = tkg & 3;

    const int barid = 1 + kg;

    const int erow = tid >> 4;
    const int ecol = (tid & 15) * 2;

    for (int t = 0; t < RNN_T; ++t) {
        const float* hp;
        size_t hstr;
        if (t == 0) { hp = h0; hstr = RNN_H; }
        else        { hp = out + (size_t)(t - 1) * RNN_H; hstr = OUT_RSTRIDE; }
        float* ot = out + (size_t)t * RNN_H;

        float2 xw = __ldcg((const float2*)(ot + (size_t)(brow + erow) * OUT_RSTRIDE
                                           + bcol + ecol));

        const float* arow = hp + (size_t)(brow + lr) * hstr + kg * 256 + lc4 * 4;

        float4 ra[8];
#pragma unroll
        for (int j = 0; j < 8; j++)
            ra[j] = __ldcg((const float4*)(arow + j * 16));

        float acc[2][4];
#pragma unroll
        for (int nb = 0; nb < 2; nb++)
#pragma unroll
            for (int i = 0; i < 4; i++) acc[nb][i] = 0.0f;

#pragma unroll
        for (int j = 0; j < 8; j++) {
            __nv_bfloat162 h0v, h1v, l0v, l1v;
            split4(ra[j], h0v, h1v, l0v, l1v);
            const int off = lr * P2_LDA + lc4 * 4 + j * 16;
            uint2 hv; hv.x = *(uint32_t*)&h0v; hv.y = *(uint32_t*)&h1v;
            uint2 lv; lv.x = *(uint32_t*)&l0v; lv.y = *(uint32_t*)&l1v;
            *(uint2*)&Ah[off] = hv;
            *(uint2*)&Al[off] = lv;
        }
        NAMED_BAR(barid);

        float4 rb[8];
#pragma unroll
        for (int j = 0; j < 8; j++)
            rb[j] = __ldcg((const float4*)(arow + 128 + j * 16));

        {
            const uint32_t bbase = (uint32_t)(kg * 256) * 2;
#pragma unroll
            for (int ks = 0; ks < 8; ++ks) {
                uint32_t ah0, ah1, ah2, ah3, al0, al1, al2, al3;
                ldsm_x4(ah0, ah1, ah2, ah3, aHi + ks * 32);
                ldsm_x4(al0, al1, al2, al3, aLo + ks * 32);
                uint32_t bh0, bh1, bh2, bh3, bl0, bl1, bl2, bl3;
                ldsm_x4(bh0, bh1, bh2, bh3, bHi + bbase + ks * 32);
                ldsm_x4(bl0, bl1, bl2, bl3, bLo + bbase + ks * 32);
                mma_bf16(acc[0], ah0, ah1, ah2, ah3, bh0, bh1);
                mma_bf16(acc[0], ah0, ah1, ah2, ah3, bl0, bl1);
                mma_bf16(acc[0], al0, al1, al2, al3, bh0, bh1);
                mma_bf16(acc[1], ah0, ah1, ah2, ah3, bh2, bh3);
                mma_bf16(acc[1], ah0, ah1, ah2, ah3, bl2, bl3);
                mma_bf16(acc[1], al0, al1, al2, al3, bh2, bh3);
            }
        }
        NAMED_BAR(barid);

#pragma unroll
        for (int j = 0; j < 8; j++) {
            __nv_bfloat162 h0v, h1v, l0v, l1v;
            split4(rb[j], h0v, h1v, l0v, l1v);
            const int off = lr * P2_LDA + lc4 * 4 + j * 16;
            uint2 hv; hv.x = *(uint32_t*)&h0v; hv.y = *(uint32_t*)&h1v;
            uint2 lv; lv.x = *(uint32_t*)&l0v; lv.y = *(uint32_t*)&l1v;
            *(uint2*)&Ah[off] = hv;
            *(uint2*)&Al[off] = lv;
        }
        NAMED_BAR(barid);

        {
            const uint32_t bbase = (uint32_t)(kg * 256 + 128) * 2;
#pragma unroll
            for (int ks = 0; ks < 8; ++ks) {
                uint32_t ah0, ah1, ah2, ah3, al0, al1, al2, al3;
                ldsm_x4(ah0, ah1, ah2, ah3, aHi + ks * 32);
                ldsm_x4(al0, al1, al2, al3, aLo + ks * 32);
                uint32_t bh0, bh1, bh2, bh3, bl0, bl1, bl2, bl3;
                ldsm_x4(bh0, bh1, bh2, bh3, bHi + bbase + ks * 32);
                ldsm_x4(bl0, bl1, bl2, bl3, bLo + bbase + ks * 32);
                mma_bf16(acc[0], ah0, ah1, ah2, ah3, bh0, bh1);
                mma_bf16(acc[0], ah0, ah1, ah2, ah3, bl0, bl1);
                mma_bf16(acc[0], al0, al1, al2, al3, bh0, bh1);
                mma_bf16(acc[1], ah0, ah1, ah2, ah3, bh2, bh3);
                mma_bf16(acc[1], ah0, ah1, ah2, ah3, bl2, bl3);
                mma_bf16(acc[1], al0, al1, al2, al3, bh2, bh3);
            }
        }

        {
            float* rg = red + kg * (P2_BM * P2_REDLD);
#pragma unroll
            for (int nb = 0; nb < 2; nb++) {
                const int col = wn + nb * 8 + tg * 2;
                *(float2*)&rg[(wm + g)     * P2_REDLD + col] =
                    make_float2(acc[nb][0], acc[nb][1]);
                *(float2*)&rg[(wm + g + 8) * P2_REDLD + col] =
                    make_float2(acc[nb][2], acc[nb][3]);
            }
        }
        __syncthreads();

        {
            float sx = xw.x, sy = xw.y;
#pragma unroll
            for (int q = 0; q < 4; q++) {
                float2 v = *(float2*)&red[q * (P2_BM * P2_REDLD)
                                          + erow * P2_REDLD + ecol];
                sx += v.x; sy += v.y;
            }
            float2 o = make_float2(tanhf(sx), tanhf(sy));
            *(float2*)(ot + (size_t)(brow + erow) * OUT_RSTRIDE + bcol + ecol) = o;
        }

        group_barrier(grp, col_);
    }
}

// ---------------------------------------------------------------------------
// Launch
// ---------------------------------------------------------------------------
extern "C" void kernel_launch(void* const* d_in, const int* in_sizes, int n_in,
                              void* d_out, int out_size)
{
    const float* x  = (const float*)d_in[0];
    const float* h0 = (const float*)d_in[1];
    const float* Wx = (const float*)d_in[2];
    const float* Wh = (const float*)d_in[3];
    const float* b  = (const float*)d_in[4];
    float* out = (float*)d_out;

    __nv_bfloat16 *wxt_hi, *wxt_lo, *wht_hi, *wht_lo, *xhi, *xlo;
    cudaGetSymbolAddress((void**)&wxt_hi, g_Wxt_hi);
    cudaGetSymbolAddress((void**)&wxt_lo, g_Wxt_lo);
    cudaGetSymbolAddress((void**)&wht_hi, g_Wht_hi);
    cudaGetSymbolAddress((void**)&wht_lo, g_Wht_lo);
    cudaGetSymbolAddress((void**)&xhi, g_x_hi);
    cudaGetSymbolAddress((void**)&xlo, g_x_lo);

    // Phase 0: weight split + transpose; x split
    {
        dim3 blk(32, 8);
        dim3 grid(RNN_H / 32, RNN_D / 32);
        convert_w_kernel<<<grid, blk>>>(Wx, wxt_hi, wxt_lo, RNN_D, RNN_H);
        convert_w_kernel<<<grid, blk>>>(Wh, wht_hi, wht_lo, RNN_H, RNN_H);
        const size_t total = (size_t)RNN_N * RNN_T * RNN_D / 4;
        split_x_kernel<<<(unsigned)(total / 256), 256>>>(x, xhi, xlo);
    }

    // Phase 1: out = x @ Wx + b (R7 config)
    {
        const int q1_smem = (3 * 2 * Q1_AT + 3 * 2 * Q1_BT) *
                            (int)sizeof(__nv_bfloat16);   // 92160
        cudaFuncSetAttribute(gemm_xw_hmma,
                             cudaFuncAttributeMaxDynamicSharedMemorySize,
                             q1_smem);
        dim3 grid(RNN_H / 128, (RNN_N * RNN_T) / 64);     // (8, 1024)
        gemm_xw_hmma<<<grid, 512, q1_smem>>>(b, out);
    }

    // Phase 2: persistent kernel over all 512 steps (R7 config, tree barrier)
    {
        const int smem_bytes =
            2 * (P2_BN * P2_LDB) * (int)sizeof(__nv_bfloat16) +
            4 * 2 * P2_ABUF * (int)sizeof(__nv_bfloat16) +
            4 * (P2_BM * P2_REDLD) * (int)sizeof(float);
        cudaFuncSetAttribute(rnn_persistent,
                             cudaFuncAttributeMaxDynamicSharedMemorySize,
                             smem_bytes);
        rnn_persistent<<<P2_NCTAS, 512, smem_bytes>>>(h0, out);
    }
}

// round 17
// speedup vs baseline: 1.0388x; 1.0388x over previous
#include <cuda_runtime.h>
#include <cuda_bf16.h>
#include <math.h>
#include <stdint.h>

// Shapes fixed by the reference:
//   x  : (N, T, D) = (128, 512, 1024)
//   h0 : (N, H)    = (128, 1024)
//   Wx : (D, H), Wh : (H, H), b : (H)
//   out: (N, T, H) fp32

#define RNN_N 128
#define RNN_T 512
#define RNN_D 1024
#define RNN_H 1024

#define OUT_RSTRIDE ((size_t)RNN_T * RNN_H)

// Phase 2 geometry (R7 — best known)
#define P2_NCTAS 128
#define P2_BM 32
#define P2_BN 32
#define P2_LDB 1032
#define P2_LDA 136
#define P2_ABUF (P2_BM * P2_LDA)
#define P2_REDLD 34

// Split, transposed weights ([n][k] layout)
__device__ __nv_bfloat16 g_Wxt_hi[RNN_H * RNN_D];
__device__ __nv_bfloat16 g_Wxt_lo[RNN_H * RNN_D];
__device__ __nv_bfloat16 g_Wht_hi[RNN_H * RNN_H];
__device__ __nv_bfloat16 g_Wht_lo[RNN_H * RNN_H];

// Pre-split x (bf16 hi/lo), row-major (M, D) with M = N*T
__device__ __nv_bfloat16 g_x_hi[(size_t)RNN_N * RNN_T * RNN_D];
__device__ __nv_bfloat16 g_x_lo[(size_t)RNN_N * RNN_T * RNN_D];

// Per-row-group barrier state (atomic + generation — R7 proven)
__device__ unsigned g_bar_count[4 * 32];
__device__ volatile unsigned g_bar_gen[4 * 32];

// ---------------------------------------------------------------------------
// helpers
// ---------------------------------------------------------------------------
__device__ __forceinline__ uint32_t cvta_smem(const void* p) {
    uint32_t a;
    asm("{ .reg .u64 t; cvta.to.shared.u64 t, %1; cvt.u32.u64 %0, t; }"
        : "=r"(a) : "l"(p));
    return a;
}

__device__ __forceinline__ void ldsm_x4(uint32_t& r0, uint32_t& r1,
                                        uint32_t& r2, uint32_t& r3,
                                        uint32_t addr) {
    asm volatile("ldmatrix.sync.aligned.m8n8.x4.shared.b16 {%0,%1,%2,%3}, [%4];"
        : "=r"(r0), "=r"(r1), "=r"(r2), "=r"(r3) : "r"(addr));
}

__device__ __forceinline__ void mma_bf16(float c[4],
    uint32_t a0, uint32_t a1, uint32_t a2, uint32_t a3,
    uint32_t b0, uint32_t b1)
{
    asm volatile(
        "mma.sync.aligned.m16n8k16.row.col.f32.bf16.bf16.f32 "
        "{%0,%1,%2,%3}, {%4,%5,%6,%7}, {%8,%9}, {%0,%1,%2,%3};"
        : "+f"(c[0]), "+f"(c[1]), "+f"(c[2]), "+f"(c[3])
        : "r"(a0), "r"(a1), "r"(a2), "r"(a3), "r"(b0), "r"(b1));
}

__device__ __forceinline__ void split4(const float4 v,
    __nv_bfloat162& h0, __nv_bfloat162& h1,
    __nv_bfloat162& l0, __nv_bfloat162& l1)
{
    h0 = __floats2bfloat162_rn(v.x, v.y);
    h1 = __floats2bfloat162_rn(v.z, v.w);
    l0 = __floats2bfloat162_rn(v.x - __bfloat162float(h0.x),
                               v.y - __bfloat162float(h0.y));
    l1 = __floats2bfloat162_rn(v.z - __bfloat162float(h1.x),
                               v.w - __bfloat162float(h1.y));
}

__device__ __forceinline__ void cp16(uint32_t dst, const void* src) {
    asm volatile("cp.async.cg.shared.global [%0], [%1], 16;"
                 :: "r"(dst), "l"(src));
}
#define CP_COMMIT() asm volatile("cp.async.commit_group;")
#define CP_WAIT1()  asm volatile("cp.async.wait_group 1;")

#define NAMED_BAR(id) asm volatile("bar.sync %0, 128;" :: "r"(id) : "memory")

// ---------------------------------------------------------------------------
// Weight convert: W (K x N, row-major) -> Wt_hi/lo (N x K, bf16 split)
// ---------------------------------------------------------------------------
__global__ __launch_bounds__(256) void convert_w_kernel(
    const float* __restrict__ W,
    __nv_bfloat16* __restrict__ Wt_hi,
    __nv_bfloat16* __restrict__ Wt_lo,
    int K, int N)
{
    __shared__ float tile[32][33];
    const int k0 = blockIdx.y * 32;
    const int n0 = blockIdx.x * 32;
    const int tx = threadIdx.x;
    const int ty = threadIdx.y;

#pragma unroll
    for (int i = 0; i < 32; i += 8)
        tile[ty + i][tx] = W[(size_t)(k0 + ty + i) * N + n0 + tx];
    __syncthreads();

#pragma unroll
    for (int i = 0; i < 32; i += 8) {
        float v = tile[tx][ty + i];
        __nv_bfloat16 h = __float2bfloat16(v);
        __nv_bfloat16 l = __float2bfloat16(v - __bfloat162float(h));
        size_t idx = (size_t)(n0 + ty + i) * K + (k0 + tx);
        Wt_hi[idx] = h;
        Wt_lo[idx] = l;
    }
}

// ---------------------------------------------------------------------------
// Split x into bf16 hi/lo global buffers (one float4 per thread)
// ---------------------------------------------------------------------------
__global__ __launch_bounds__(256) void split_x_kernel(
    const float* __restrict__ x,
    __nv_bfloat16* __restrict__ xhi,
    __nv_bfloat16* __restrict__ xlo)
{
    const size_t i = ((size_t)blockIdx.x * blockDim.x + threadIdx.x) * 4;
    float4 v = *(const float4*)(x + i);
    __nv_bfloat162 h0, h1, l0, l1;
    split4(v, h0, h1, l0, l1);
    uint2 hv; hv.x = *(uint32_t*)&h0; hv.y = *(uint32_t*)&h1;
    uint2 lv; lv.x = *(uint32_t*)&l0; lv.y = *(uint32_t*)&l1;
    *(uint2*)(xhi + i) = hv;
    *(uint2*)(xlo + i) = lv;
}

// ---------------------------------------------------------------------------
// Phase 1 (R7 exact, 1.105ms): out = x @ Wx + b, all-bf16, cp.async 3-stage.
// CTA 64x128, BK=32, 512 thr (16 warps 4m x 4n), warp tile 16x32.
// ---------------------------------------------------------------------------
#define Q1_LDK 40
#define Q1_AT (64 * Q1_LDK)
#define Q1_BT (128 * Q1_LDK)

__global__ __launch_bounds__(512) void gemm_xw_hmma(
    const float* __restrict__ bias,
    float* __restrict__ C)
{
    extern __shared__ __nv_bfloat16 q1sm[];
    __nv_bfloat16* AsHi = q1sm;
    __nv_bfloat16* AsLo = AsHi + 3 * Q1_AT;
    __nv_bfloat16* BsHi = AsLo + 3 * Q1_AT;
    __nv_bfloat16* BsLo = BsHi + 3 * Q1_BT;

    const int tid  = threadIdx.x;
    const int warp = tid >> 5;
    const int lane = tid & 31;
    const int g  = lane >> 2;
    const int tg = lane & 3;
    const int wm = (warp & 3) * 16;
    const int wn = (warp >> 2) * 32;

    const int brow = blockIdx.y * 64;
    const int bcol = blockIdx.x * 128;

    const int lrow = tid >> 2;
    const int lseg = (tid & 3) * 8;

    const __nv_bfloat16* Ahp = g_x_hi + (size_t)(brow + lrow) * RNN_D + lseg;
    const __nv_bfloat16* Alp = g_x_lo + (size_t)(brow + lrow) * RNN_D + lseg;
    const __nv_bfloat16* Bhp = g_Wxt_hi + (size_t)(bcol + lrow) * RNN_D + lseg;
    const __nv_bfloat16* Blp = g_Wxt_lo + (size_t)(bcol + lrow) * RNN_D + lseg;

    const uint32_t aDstHi = cvta_smem(AsHi) + (lrow * Q1_LDK + lseg) * 2;
    const uint32_t aDstLo = aDstHi + 3 * Q1_AT * 2;
    const uint32_t bDstHi = cvta_smem(BsHi) + (lrow * Q1_LDK + lseg) * 2;
    const uint32_t bDstLo = bDstHi + 3 * Q1_BT * 2;

    const uint32_t aHi0 = cvta_smem(AsHi) +
        (((wm + (lane & 15)) * Q1_LDK + ((lane >> 4) & 1) * 8) * 2);
    const uint32_t aLo0 = aHi0 + 3 * Q1_AT * 2;
    const uint32_t bHi0 = cvta_smem(BsHi) +
        (((wn + (lane & 7) + ((lane >> 4) & 1) * 8) * Q1_LDK +
          ((lane >> 3) & 1) * 8) * 2);
    const uint32_t bLo0 = bHi0 + 3 * Q1_BT * 2;

    float acc[4][4];
#pragma unroll
    for (int j = 0; j < 4; j++)
#pragma unroll
        for (int i = 0; i < 4; i++) acc[j][i] = 0.0f;

    auto issue = [&](int s) {
        const int buf = s % 3;
        const int kt = s * 32;
        if (tid < 256) {
            cp16(aDstHi + buf * (Q1_AT * 2), Ahp + kt);
            cp16(aDstLo + buf * (Q1_AT * 2), Alp + kt);
        }
        cp16(bDstHi + buf * (Q1_BT * 2), Bhp + kt);
        cp16(bDstLo + buf * (Q1_BT * 2), Blp + kt);
    };

    issue(0); CP_COMMIT();
    issue(1); CP_COMMIT();

    for (int i = 0; i < 32; ++i) {
        CP_WAIT1();
        __syncthreads();
        if (i + 2 < 32) issue(i + 2);
        CP_COMMIT();

        const uint32_t aoff = (uint32_t)(i % 3) * (Q1_AT * 2);
        const uint32_t boff = (uint32_t)(i % 3) * (Q1_BT * 2);
#pragma unroll
        for (int ks = 0; ks < 2; ++ks) {
            uint32_t ah0, ah1, ah2, ah3, al0, al1, al2, al3;
            ldsm_x4(ah0, ah1, ah2, ah3, aHi0 + aoff + ks * 32);
            ldsm_x4(al0, al1, al2, al3, aLo0 + aoff + ks * 32);
#pragma unroll
            for (int pr = 0; pr < 2; ++pr) {
                uint32_t bh0, bh1, bh2, bh3, bl0, bl1, bl2, bl3;
                ldsm_x4(bh0, bh1, bh2, bh3, bHi0 + boff + pr * (16 * Q1_LDK * 2) + ks * 32);
                ldsm_x4(bl0, bl1, bl2, bl3, bLo0 + boff + pr * (16 * Q1_LDK * 2) + ks * 32);
                mma_bf16(acc[2 * pr],     ah0, ah1, ah2, ah3, bh0, bh1);
                mma_bf16(acc[2 * pr],     ah0, ah1, ah2, ah3, bl0, bl1);
                mma_bf16(acc[2 * pr],     al0, al1, al2, al3, bh0, bh1);
                mma_bf16(acc[2 * pr + 1], ah0, ah1, ah2, ah3, bh2, bh3);
                mma_bf16(acc[2 * pr + 1], ah0, ah1, ah2, ah3, bl2, bl3);
                mma_bf16(acc[2 * pr + 1], al0, al1, al2, al3, bh2, bh3);
            }
        }
    }

#pragma unroll
    for (int j = 0; j < 4; j++) {
        const int col = bcol + wn + j * 8 + tg * 2;
        const float b0 = __ldg(bias + col);
        const float b1 = __ldg(bias + col + 1);
        const int r0 = brow + wm + g;
        float2 o0 = make_float2(acc[j][0] + b0, acc[j][1] + b1);
        float2 o1 = make_float2(acc[j][2] + b0, acc[j][3] + b1);
        *(float2*)&C[(size_t)r0 * RNN_H + col]       = o0;
        *(float2*)&C[(size_t)(r0 + 8) * RNN_H + col] = o1;
    }
}

// ---------------------------------------------------------------------------
// Per-row-group barrier (R7 proven, monolithic)
// ---------------------------------------------------------------------------
__device__ __forceinline__ void group_barrier(int grp)
{
    __syncthreads();
    if (threadIdx.x == 0) {
        const int s = grp * 32;
        __threadfence();
        unsigned gen = g_bar_gen[s];
        unsigned old = atomicAdd(&g_bar_count[s], 1u);
        if (old == 31u) {
            g_bar_count[s] = 0;
            __threadfence();
            g_bar_gen[s] = gen + 1;
        } else {
            while (g_bar_gen[s] == gen) { }
            __threadfence();
        }
    }
    __syncthreads();
}

// ---------------------------------------------------------------------------
// Phase 2 persistent kernel — R7 structure, but the 3 bf16x3 terms use
// SEPARATE accumulators (6 independent mma chains per warp instead of 2),
// cutting the per-chunk dependent-mma chain 24 -> 8. Summed in epilogue.
// ---------------------------------------------------------------------------
__global__ __launch_bounds__(512) void rnn_persistent(
    const float* __restrict__ h0,
    float* __restrict__ out)
{
    extern __shared__ char sm[];
    __nv_bfloat16* Bs_hi = (__nv_bfloat16*)sm;
    __nv_bfloat16* Bs_lo = Bs_hi + P2_BN * P2_LDB;
    __nv_bfloat16* A_all = Bs_lo + P2_BN * P2_LDB;
    float* red = (float*)(A_all + 4 * 2 * P2_ABUF);

    const int tid  = threadIdx.x;
    const int warp = tid >> 5;
    const int lane = tid & 31;
    const int g  = lane >> 2;
    const int tg = lane & 3;
    const int kg = warp >> 2;
    const int w2 = warp & 3;
    const int wm = (w2 & 1) * 16;
    const int wn = (w2 >> 1) * 16;

    const int bx   = blockIdx.x;
    const int bcol = (bx & 31) * P2_BN;
    const int grp  = bx >> 5;
    const int brow = grp * P2_BM;

    {
        const uint4* GH = (const uint4*)(g_Wht_hi + (size_t)bcol * RNN_H);
        const uint4* GL = (const uint4*)(g_Wht_lo + (size_t)bcol * RNN_H);
        for (int idx = tid; idx < 4096; idx += 512) {
            const int r  = idx >> 7;
            const int k8 = (idx & 127) * 8;
            uint4 vh = GH[(size_t)r * 128 + (idx & 127)];
            uint4 vl = GL[(size_t)r * 128 + (idx & 127)];
            *(uint4*)((char*)Bs_hi + r * (P2_LDB * 2) + k8 * 2) = vh;
            *(uint4*)((char*)Bs_lo + r * (P2_LDB * 2) + k8 * 2) = vl;
        }
    }
    __syncthreads();

    __nv_bfloat16* Ah = A_all + kg * (2 * P2_ABUF);
    __nv_bfloat16* Al = Ah + P2_ABUF;

    const uint32_t aHi = cvta_smem(Ah) +
        (((wm + (lane & 15)) * P2_LDA + ((lane >> 4) & 1) * 8) * 2);
    const uint32_t aLo = aHi + P2_ABUF * 2;
    const uint32_t bHi = cvta_smem(Bs_hi) +
        (((wn + (lane & 7) + ((lane >> 4) & 1) * 8) * P2_LDB +
          ((lane >> 3) & 1) * 8) * 2);
    const uint32_t bLo = bHi + (P2_BN * P2_LDB) * 2;

    const int tkg = tid & 127;
    const int lr  = tkg >> 2;
    const int lc4 = tkg & 3;

    const int barid = 1 + kg;

    const int erow = tid >> 4;
    const int ecol = (tid & 15) * 2;

    for (int t = 0; t < RNN_T; ++t) {
        const float* hp;
        size_t hstr;
        if (t == 0) { hp = h0; hstr = RNN_H; }
        else        { hp = out + (size_t)(t - 1) * RNN_H; hstr = OUT_RSTRIDE; }
        float* ot = out + (size_t)t * RNN_H;

        float2 xw = __ldcg((const float2*)(ot + (size_t)(brow + erow) * OUT_RSTRIDE
                                           + bcol + ecol));

        const float* arow = hp + (size_t)(brow + lr) * hstr + kg * 256 + lc4 * 4;

        float4 ra[8];
#pragma unroll
        for (int j = 0; j < 8; j++)
            ra[j] = __ldcg((const float4*)(arow + j * 16));

        // three independent accumulator sets per n8 (hi*hi / hi*lo / lo*hi)
        float accA[2][4], accB[2][4], accC[2][4];
#pragma unroll
        for (int nb = 0; nb < 2; nb++)
#pragma unroll
            for (int i = 0; i < 4; i++) {
                accA[nb][i] = 0.0f; accB[nb][i] = 0.0f; accC[nb][i] = 0.0f;
            }

#pragma unroll
        for (int j = 0; j < 8; j++) {
            __nv_bfloat162 h0v, h1v, l0v, l1v;
            split4(ra[j], h0v, h1v, l0v, l1v);
            const int off = lr * P2_LDA + lc4 * 4 + j * 16;
            uint2 hv; hv.x = *(uint32_t*)&h0v; hv.y = *(uint32_t*)&h1v;
            uint2 lv; lv.x = *(uint32_t*)&l0v; lv.y = *(uint32_t*)&l1v;
            *(uint2*)&Ah[off] = hv;
            *(uint2*)&Al[off] = lv;
        }
        NAMED_BAR(barid);

        float4 rb[8];
#pragma unroll
        for (int j = 0; j < 8; j++)
            rb[j] = __ldcg((const float4*)(arow + 128 + j * 16));

        {
            const uint32_t bbase = (uint32_t)(kg * 256) * 2;
#pragma unroll
            for (int ks = 0; ks < 8; ++ks) {
                uint32_t ah0, ah1, ah2, ah3, al0, al1, al2, al3;
                ldsm_x4(ah0, ah1, ah2, ah3, aHi + ks * 32);
                ldsm_x4(al0, al1, al2, al3, aLo + ks * 32);
                uint32_t bh0, bh1, bh2, bh3, bl0, bl1, bl2, bl3;
                ldsm_x4(bh0, bh1, bh2, bh3, bHi + bbase + ks * 32);
                ldsm_x4(bl0, bl1, bl2, bl3, bLo + bbase + ks * 32);
                mma_bf16(accA[0], ah0, ah1, ah2, ah3, bh0, bh1);
                mma_bf16(accB[0], ah0, ah1, ah2, ah3, bl0, bl1);
                mma_bf16(accC[0], al0, al1, al2, al3, bh0, bh1);
                mma_bf16(accA[1], ah0, ah1, ah2, ah3, bh2, bh3);
                mma_bf16(accB[1], ah0, ah1, ah2, ah3, bl2, bl3);
                mma_bf16(accC[1], al0, al1, al2, al3, bh2, bh3);
            }
        }
        NAMED_BAR(barid);

#pragma unroll
        for (int j = 0; j < 8; j++) {
            __nv_bfloat162 h0v, h1v, l0v, l1v;
            split4(rb[j], h0v, h1v, l0v, l1v);
            const int off = lr * P2_LDA + lc4 * 4 + j * 16;
            uint2 hv; hv.x = *(uint32_t*)&h0v; hv.y = *(uint32_t*)&h1v;
            uint2 lv; lv.x = *(uint32_t*)&l0v; lv.y = *(uint32_t*)&l1v;
            *(uint2*)&Ah[off] = hv;
            *(uint2*)&Al[off] = lv;
        }
        NAMED_BAR(barid);

        {
            const uint32_t bbase = (uint32_t)(kg * 256 + 128) * 2;
#pragma unroll
            for (int ks = 0; ks < 8; ++ks) {
                uint32_t ah0, ah1, ah2, ah3, al0, al1, al2, al3;
                ldsm_x4(ah0, ah1, ah2, ah3, aHi + ks * 32);
                ldsm_x4(al0, al1, al2, al3, aLo + ks * 32);
                uint32_t bh0, bh1, bh2, bh3, bl0, bl1, bl2, bl3;
                ldsm_x4(bh0, bh1, bh2, bh3, bHi + bbase + ks * 32);
                ldsm_x4(bl0, bl1, bl2, bl3, bLo + bbase + ks * 32);
                mma_bf16(accA[0], ah0, ah1, ah2, ah3, bh0, bh1);
                mma_bf16(accB[0], ah0, ah1, ah2, ah3, bl0, bl1);
                mma_bf16(accC[0], al0, al1, al2, al3, bh0, bh1);
                mma_bf16(accA[1], ah0, ah1, ah2, ah3, bh2, bh3);
                mma_bf16(accB[1], ah0, ah1, ah2, ah3, bl2, bl3);
                mma_bf16(accC[1], al0, al1, al2, al3, bh2, bh3);
            }
        }

        {
            float* rg = red + kg * (P2_BM * P2_REDLD);
#pragma unroll
            for (int nb = 0; nb < 2; nb++) {
                const int col = wn + nb * 8 + tg * 2;
                *(float2*)&rg[(wm + g)     * P2_REDLD + col] =
                    make_float2(accA[nb][0] + accB[nb][0] + accC[nb][0],
                                accA[nb][1] + accB[nb][1] + accC[nb][1]);
                *(float2*)&rg[(wm + g + 8) * P2_REDLD + col] =
                    make_float2(accA[nb][2] + accB[nb][2] + accC[nb][2],
                                accA[nb][3] + accB[nb][3] + accC[nb][3]);
            }
        }
        __syncthreads();

        {
            float sx = xw.x, sy = xw.y;
#pragma unroll
            for (int q = 0; q < 4; q++) {
                float2 v = *(float2*)&red[q * (P2_BM * P2_REDLD)
                                          + erow * P2_REDLD + ecol];
                sx += v.x; sy += v.y;
            }
            float2 o = make_float2(tanhf(sx), tanhf(sy));
            *(float2*)(ot + (size_t)(brow + erow) * OUT_RSTRIDE + bcol + ecol) = o;
        }

        if (t + 1 < RNN_T)
            group_barrier(grp);
    }
}

// ---------------------------------------------------------------------------
// Launch
// ---------------------------------------------------------------------------
extern "C" void kernel_launch(void* const* d_in, const int* in_sizes, int n_in,
                              void* d_out, int out_size)
{
    const float* x  = (const float*)d_in[0];
    const float* h0 = (const float*)d_in[1];
    const float* Wx = (const float*)d_in[2];
    const float* Wh = (const float*)d_in[3];
    const float* b  = (const float*)d_in[4];
    float* out = (float*)d_out;

    __nv_bfloat16 *wxt_hi, *wxt_lo, *wht_hi, *wht_lo, *xhi, *xlo;
    cudaGetSymbolAddress((void**)&wxt_hi, g_Wxt_hi);
    cudaGetSymbolAddress((void**)&wxt_lo, g_Wxt_lo);
    cudaGetSymbolAddress((void**)&wht_hi, g_Wht_hi);
    cudaGetSymbolAddress((void**)&wht_lo, g_Wht_lo);
    cudaGetSymbolAddress((void**)&xhi, g_x_hi);
    cudaGetSymbolAddress((void**)&xlo, g_x_lo);

    // Phase 0: weight split + transpose; x split
    {
        dim3 blk(32, 8);
        dim3 grid(RNN_H / 32, RNN_D / 32);
        convert_w_kernel<<<grid, blk>>>(Wx, wxt_hi, wxt_lo, RNN_D, RNN_H);
        convert_w_kernel<<<grid, blk>>>(Wh, wht_hi, wht_lo, RNN_H, RNN_H);
        const size_t total = (size_t)RNN_N * RNN_T * RNN_D / 4;
        split_x_kernel<<<(unsigned)(total / 256), 256>>>(x, xhi, xlo);
    }

    // Phase 1: out = x @ Wx + b (R7 config)
    {
        const int q1_smem = (3 * 2 * Q1_AT + 3 * 2 * Q1_BT) *
                            (int)sizeof(__nv_bfloat16);   // 92160
        cudaFuncSetAttribute(gemm_xw_hmma,
                             cudaFuncAttributeMaxDynamicSharedMemorySize,
                             q1_smem);
        dim3 grid(RNN_H / 128, (RNN_N * RNN_T) / 64);     // (8, 1024)
        gemm_xw_hmma<<<grid, 512, q1_smem>>>(b, out);
    }

    // Phase 2: persistent kernel over all 512 steps
    {
        const int smem_bytes =
            2 * (P2_BN * P2_LDB) * (int)sizeof(__nv_bfloat16) +
            4 * 2 * P2_ABUF * (int)sizeof(__nv_bfloat16) +
            4 * (P2_BM * P2_REDLD) * (int)sizeof(float);
        cudaFuncSetAttribute(rnn_persistent,
                             cudaFuncAttributeMaxDynamicSharedMemorySize,
                             smem_bytes);
        rnn_persistent<<<P2_NCTAS, 512, smem_bytes>>>(h0, out);
    }
}